// round 2
// baseline (speedup 1.0000x reference)
#include <cuda_runtime.h>

// ----------------------------------------------------------------------------
// Cross_MultiAttention — algebraically folded.
//
// Key identity: all Q/K/V are affine in a 6- or 12-dim per-pixel feature, so
// attention logits per head reduce to  (f1[s] @ M_h + v_h) . fcat[j]  with
// M_h [6,12], and att@V folds through Wp into per-head [6,12] P matrices.
// One fused pass, online softmax, f32x2 packed FMA.
// ----------------------------------------------------------------------------

#define SCALE_EMB 0.044194173824159216f   // 512^-0.5

typedef unsigned long long u64;

struct Params {
    float M[8][6][12];      // SCALE * A_q_h @ A_k_h^T
    float v[8][12];         // SCALE * A_k_h @ bq_eff_h
    float P[2][8][6][12];   // Wp (branch half, head block) @ A_v_h^T
    float C[6];             // bp + (Wp1+Wp2) @ bv_eff
};

__device__ float g_Aq[6][512];
__device__ float g_Ak[12][512];
__device__ float g_Av[12][512];
__device__ float g_bqe[512];
__device__ float g_bke[512];
__device__ float g_bve[512];
__device__ Params g_params;

// ---- packed f32x2 helpers (Blackwell FFMA2 path) ----
__device__ __forceinline__ u64 pack2(float lo, float hi) {
    u64 r; asm("mov.b64 %0, {%1,%2};" : "=l"(r) : "f"(lo), "f"(hi)); return r;
}
__device__ __forceinline__ void unpack2(u64 v, float& lo, float& hi) {
    asm("mov.b64 {%0,%1}, %2;" : "=f"(lo), "=f"(hi) : "l"(v));
}
__device__ __forceinline__ u64 fma2(u64 a, u64 b, u64 c) {
    u64 d; asm("fma.rn.f32x2 %0, %1, %2, %3;" : "=l"(d) : "l"(a), "l"(b), "l"(c)); return d;
}
__device__ __forceinline__ u64 mul2(u64 a, u64 b) {
    u64 d; asm("mul.rn.f32x2 %0, %1, %2;" : "=l"(d) : "l"(a), "l"(b)); return d;
}

// ----------------------------------------------------------------------------
// Precompute 1: fold W_emb-like [R,512] through W [512,512]:
//   Aout[k][e] = sum_m We[k][m] * W[m][e]
//   bout[e]    = bw[e] + sum_m be[m] * W[m][e]
// ----------------------------------------------------------------------------
template <int R>
__device__ void fold_body(float* sE, float* sb,
                          const float* __restrict__ We, const float* __restrict__ be,
                          const float* __restrict__ W,  const float* __restrict__ bw,
                          float (*Aout)[512], float* bout)
{
    int tid = threadIdx.x;
    for (int i = tid; i < R * 512; i += blockDim.x) sE[i] = We[i];
    for (int i = tid; i < 512; i += blockDim.x) sb[i] = be[i];
    __syncthreads();
    int e = tid;
    float acc[R];
#pragma unroll
    for (int k = 0; k < R; k++) acc[k] = 0.f;
    float bacc = bw[e];
#pragma unroll 4
    for (int m = 0; m < 512; m++) {
        float w = W[m * 512 + e];
        bacc += sb[m] * w;
#pragma unroll
        for (int k = 0; k < R; k++) acc[k] += sE[k * 512 + m] * w;
    }
#pragma unroll
    for (int k = 0; k < R; k++) Aout[k][e] = acc[k];
    bout[e] = bacc;
}

__global__ void precompute_fold(const float* __restrict__ W_emb,  const float* __restrict__ b_emb,
                                const float* __restrict__ W_emb2, const float* __restrict__ b_emb2,
                                const float* __restrict__ Wq, const float* __restrict__ bq,
                                const float* __restrict__ Wk, const float* __restrict__ bk,
                                const float* __restrict__ Wv, const float* __restrict__ bv)
{
    __shared__ float sE[12 * 512];
    __shared__ float sb[512];
    if (blockIdx.x == 0)      fold_body<6>(sE, sb, W_emb,  b_emb,  Wq, bq, g_Aq, g_bqe);
    else if (blockIdx.x == 1) fold_body<12>(sE, sb, W_emb2, b_emb2, Wk, bk, g_Ak, g_bke);
    else                      fold_body<12>(sE, sb, W_emb2, b_emb2, Wv, bv, g_Av, g_bve);
}

// ----------------------------------------------------------------------------
// Precompute 2: tiny per-head matrices.
// ----------------------------------------------------------------------------
__global__ void precompute_small(const float* __restrict__ Wp, const float* __restrict__ bp)
{
    int idx = blockIdx.x * blockDim.x + threadIdx.x;
    if (idx < 576) {                                   // M[h][k][c]
        int h = idx / 72, r = idx % 72, k = r / 12, c = r % 12;
        float s = 0.f;
#pragma unroll 4
        for (int d = 0; d < 64; d++) s += g_Aq[k][h * 64 + d] * g_Ak[c][h * 64 + d];
        g_params.M[h][k][c] = SCALE_EMB * s;
    } else if (idx < 672) {                            // v[h][c]
        int t = idx - 576, h = t / 12, c = t % 12;
        float s = 0.f;
#pragma unroll 4
        for (int d = 0; d < 64; d++) s += g_bqe[h * 64 + d] * g_Ak[c][h * 64 + d];
        g_params.v[h][c] = SCALE_EMB * s;
    } else if (idx < 1824) {                           // P[br][h][o][c]
        int t = idx - 672, br = t / 576, r = t % 576;
        int h = r / 72, q = r % 72, o = q / 12, c = q % 12;
        float s = 0.f;
#pragma unroll 4
        for (int d = 0; d < 64; d++)
            s += Wp[o * 1024 + br * 512 + h * 64 + d] * g_Av[c][h * 64 + d];
        g_params.P[br][h][o][c] = s;
    } else if (idx < 1830) {                           // C[o]
        int o = idx - 1824;
        float s = bp[o];
#pragma unroll 4
        for (int e = 0; e < 512; e++)
            s += (Wp[o * 1024 + e] + Wp[o * 1024 + 512 + e]) * g_bve[e];
        g_params.C[o] = s;
    }
}

// ----------------------------------------------------------------------------
// Main fused kernel: one CTA per 16x16 tile (512 CTAs), one thread per query
// pixel s. Online softmax over j in one pass; both branches per head iter.
// ----------------------------------------------------------------------------
__global__ __launch_bounds__(256, 2)
void cross_attn_main(const float* __restrict__ img1, const float* __restrict__ img2,
                     float* __restrict__ out)
{
    __shared__ __align__(16) u64 sF[256][6];   // fcat rows packed f32x2, 48B/row
    __shared__ Params sp;

    int b  = blockIdx.x;                 // bi*64 + th*8 + tw
    int bi = b >> 6, th = (b >> 3) & 7, tw = b & 7;
    int s  = threadIdx.x;
    int y  = s >> 4, x = s & 15;
    int base = bi * 6 * 16384 + (th * 16 + y) * 128 + (tw * 16 + x);

    float f1r[6], f2r[6];
#pragma unroll
    for (int c = 0; c < 6; c++) {
        f1r[c] = img1[base + c * 16384];
        f2r[c] = img2[base + c * 16384];
    }
#pragma unroll
    for (int c = 0; c < 3; c++) {
        sF[s][c]     = pack2(f1r[2 * c], f1r[2 * c + 1]);
        sF[s][3 + c] = pack2(f2r[2 * c], f2r[2 * c + 1]);
    }
    {
        float* dst = (float*)&sp;
        const float* src = (const float*)&g_params;
        for (int i = s; i < (int)(sizeof(Params) / 4); i += 256) dst[i] = src[i];
    }
    __syncthreads();

    float outacc[6];
#pragma unroll
    for (int o = 0; o < 6; o++) outacc[o] = sp.C[o];

    for (int h = 0; h < 8; h++) {
        // g = f @ M_h + v_h  for both branches
        float g1f[12], g2f[12];
#pragma unroll
        for (int c = 0; c < 12; c++) {
            float a = sp.v[h][c], bb = a;
#pragma unroll
            for (int k = 0; k < 6; k++) {
                float m = sp.M[h][k][c];
                a  += f1r[k] * m;
                bb += f2r[k] * m;
            }
            g1f[c] = a; g2f[c] = bb;
        }
        u64 g1[6], g2[6], G1[6], G2[6];
#pragma unroll
        for (int c = 0; c < 6; c++) {
            g1[c] = pack2(g1f[2 * c], g1f[2 * c + 1]);
            g2[c] = pack2(g2f[2 * c], g2f[2 * c + 1]);
            G1[c] = 0ull; G2[c] = 0ull;
        }
        float l1 = 0.f, l2 = 0.f;

        // Online pass over keys. Logits are O(0.1) by construction (weights
        // scaled 0.02, folded twice), so exp() without max-subtraction is safe
        // and exactly matches softmax.
#pragma unroll 4
        for (int j = 0; j < 256; j++) {
            const ulonglong2* rp = (const ulonglong2*)(&sF[j][0]);
            ulonglong2 q0 = rp[0], q1 = rp[1], q2 = rp[2];  // broadcast LDS.128 x3
            u64 f0 = q0.x, fv1 = q0.y, fv2 = q1.x, f3 = q1.y, f4 = q2.x, f5 = q2.y;

            u64 a1 = mul2(g1[0], f0), a2 = mul2(g2[0], f0);
            a1 = fma2(g1[1], fv1, a1); a2 = fma2(g2[1], fv1, a2);
            a1 = fma2(g1[2], fv2, a1); a2 = fma2(g2[2], fv2, a2);
            a1 = fma2(g1[3], f3,  a1); a2 = fma2(g2[3], f3,  a2);
            a1 = fma2(g1[4], f4,  a1); a2 = fma2(g2[4], f4,  a2);
            a1 = fma2(g1[5], f5,  a1); a2 = fma2(g2[5], f5,  a2);

            float lo, hi;
            unpack2(a1, lo, hi); float p1 = __expf(lo + hi);
            unpack2(a2, lo, hi); float p2 = __expf(lo + hi);
            l1 += p1; l2 += p2;
            u64 pp1 = pack2(p1, p1), pp2 = pack2(p2, p2);

            G1[0] = fma2(pp1, f0,  G1[0]); G2[0] = fma2(pp2, f0,  G2[0]);
            G1[1] = fma2(pp1, fv1, G1[1]); G2[1] = fma2(pp2, fv1, G2[1]);
            G1[2] = fma2(pp1, fv2, G1[2]); G2[2] = fma2(pp2, fv2, G2[2]);
            G1[3] = fma2(pp1, f3,  G1[3]); G2[3] = fma2(pp2, f3,  G2[3]);
            G1[4] = fma2(pp1, f4,  G1[4]); G2[4] = fma2(pp2, f4,  G2[4]);
            G1[5] = fma2(pp1, f5,  G1[5]); G2[5] = fma2(pp2, f5,  G2[5]);
        }

        float inv1 = 1.0f / l1, inv2 = 1.0f / l2;
        float Gn1[12], Gn2[12];
#pragma unroll
        for (int c = 0; c < 6; c++) {
            float a, bb;
            unpack2(G1[c], a, bb); Gn1[2 * c] = a * inv1; Gn1[2 * c + 1] = bb * inv1;
            unpack2(G2[c], a, bb); Gn2[2 * c] = a * inv2; Gn2[2 * c + 1] = bb * inv2;
        }
#pragma unroll
        for (int o = 0; o < 6; o++) {
            float acc = outacc[o];
#pragma unroll
            for (int c = 0; c < 12; c++) acc += Gn1[c] * sp.P[0][h][o][c];
#pragma unroll
            for (int c = 0; c < 12; c++) acc += Gn2[c] * sp.P[1][h][o][c];
            outacc[o] = acc;
        }
    }

#pragma unroll
    for (int o = 0; o < 6; o++) out[base + o * 16384] = outacc[o];
}

// ----------------------------------------------------------------------------
extern "C" void kernel_launch(void* const* d_in, const int* in_sizes, int n_in,
                              void* d_out, int out_size)
{
    const float* img1   = (const float*)d_in[0];
    const float* img2   = (const float*)d_in[1];
    const float* W_emb  = (const float*)d_in[2];
    const float* b_emb  = (const float*)d_in[3];
    const float* W_emb2 = (const float*)d_in[4];
    const float* b_emb2 = (const float*)d_in[5];
    const float* Wq     = (const float*)d_in[6];
    const float* bq     = (const float*)d_in[7];
    const float* Wk     = (const float*)d_in[8];
    const float* bk     = (const float*)d_in[9];
    const float* Wv     = (const float*)d_in[10];
    const float* bv     = (const float*)d_in[11];
    const float* Wp     = (const float*)d_in[12];
    const float* bp     = (const float*)d_in[13];
    float* out = (float*)d_out;

    precompute_fold<<<3, 512>>>(W_emb, b_emb, W_emb2, b_emb2, Wq, bq, Wk, bk, Wv, bv);
    precompute_small<<<2, 1024>>>(Wp, bp);
    cross_attn_main<<<512, 256>>>(img1, img2, out);
}

// round 3
// speedup vs baseline: 1.1907x; 1.1907x over previous
#include <cuda_runtime.h>

// ----------------------------------------------------------------------------
// Cross_MultiAttention — algebraically folded, dual-lane (branch-pair) f32x2.
//
// logit_h,br(s,j) = (f_br[s] @ M_h + v_h) . fcat[j]   with M_h [6,12]
// out folds att@V through Wp into per-(head,branch) [6,12] P matrices.
// Both branches of a head ride the two lanes of f32x2: fcat duplicated
// per-lane in smem, g/G packed (br1,br2). log2e*SCALE prefolded -> bare ex2.
// ----------------------------------------------------------------------------

#define SCALE_EMB 0.044194173824159216f   // 512^-0.5
#define LOG2E     1.4426950408889634f

typedef unsigned long long u64;

struct Params {
    float M[8][6][12];      // LOG2E*SCALE * A_q_h @ A_k_h^T
    float v[8][12];         // LOG2E*SCALE * bq_eff_h @ A_k_h^T
    u64   Pp[8][6][12];     // pack2(P_br1[h][o][c], P_br2[h][o][c])
    float C[6];             // bp + (Wp1+Wp2) @ bv_eff
};

__device__ float g_part[3][8][13][512];   // per-m-chunk partial folds (row12 = bias)
__device__ float g_A[3][13][512];         // folded: [0]=Aq(6)+bqe, [1]=Ak(12)+bke, [2]=Av(12)+bve
__device__ Params g_params;

// ---- packed f32x2 helpers ----
__device__ __forceinline__ u64 pack2(float lo, float hi) {
    u64 r; asm("mov.b64 %0, {%1,%2};" : "=l"(r) : "f"(lo), "f"(hi)); return r;
}
__device__ __forceinline__ void unpack2(u64 v, float& lo, float& hi) {
    asm("mov.b64 {%0,%1}, %2;" : "=f"(lo), "=f"(hi) : "l"(v));
}
__device__ __forceinline__ u64 fma2(u64 a, u64 b, u64 c) {
    u64 d; asm("fma.rn.f32x2 %0, %1, %2, %3;" : "=l"(d) : "l"(a), "l"(b), "l"(c)); return d;
}
__device__ __forceinline__ u64 mul2(u64 a, u64 b) {
    u64 d; asm("mul.rn.f32x2 %0, %1, %2;" : "=l"(d) : "l"(a), "l"(b)); return d;
}
__device__ __forceinline__ u64 add2(u64 a, u64 b) {
    u64 d; asm("add.rn.f32x2 %0, %1, %2;" : "=l"(d) : "l"(a), "l"(b)); return d;
}
__device__ __forceinline__ float ex2f(float x) {
    float y; asm("ex2.approx.ftz.f32 %0, %1;" : "=f"(y) : "f"(x)); return y;
}
__device__ __forceinline__ float rcpf(float x) {
    float y; asm("rcp.approx.ftz.f32 %0, %1;" : "=f"(y) : "f"(x)); return y;
}

// ----------------------------------------------------------------------------
// Precompute 1a: partial fold over a 64-wide m chunk.
//   g_part[mat][chunk][k][e] = sum_{m in chunk} We[k][m] * W[m][e]
//   row 12 uses be[m] (bias fold).
// grid = 24 (3 matrices x 8 chunks), block = 512.
// ----------------------------------------------------------------------------
__global__ void fold_partial(const float* __restrict__ W_emb,  const float* __restrict__ b_emb,
                             const float* __restrict__ W_emb2, const float* __restrict__ b_emb2,
                             const float* __restrict__ Wq, const float* __restrict__ Wk,
                             const float* __restrict__ Wv)
{
    int mat = blockIdx.x >> 3, chunk = blockIdx.x & 7;
    const float* We = (mat == 0) ? W_emb : W_emb2;
    const float* be = (mat == 0) ? b_emb : b_emb2;
    const float* W  = (mat == 0) ? Wq : (mat == 1 ? Wk : Wv);
    int R = (mat == 0) ? 6 : 12;

    __shared__ float sE[12][64];
    __shared__ float sb[64];
    int tid = threadIdx.x;
    int mc0 = chunk * 64;
    for (int i = tid; i < R * 64; i += 512) {
        int k = i >> 6, mm = i & 63;
        sE[k][mm] = We[k * 512 + mc0 + mm];
    }
    if (tid < 64) sb[tid] = be[mc0 + tid];
    __syncthreads();

    int e = tid;
    float acc[12];
#pragma unroll
    for (int k = 0; k < 12; k++) acc[k] = 0.f;
    float bacc = 0.f;
    if (R == 6) {
#pragma unroll 8
        for (int mm = 0; mm < 64; mm++) {
            float w = W[(mc0 + mm) * 512 + e];
            bacc += sb[mm] * w;
#pragma unroll
            for (int k = 0; k < 6; k++) acc[k] += sE[k][mm] * w;
        }
    } else {
#pragma unroll 4
        for (int mm = 0; mm < 64; mm++) {
            float w = W[(mc0 + mm) * 512 + e];
            bacc += sb[mm] * w;
#pragma unroll
            for (int k = 0; k < 12; k++) acc[k] += sE[k][mm] * w;
        }
    }
    for (int k = 0; k < R; k++) g_part[mat][chunk][k][e] = acc[k];
    g_part[mat][chunk][12][e] = bacc;
}

// ----------------------------------------------------------------------------
// Precompute 1b: deterministic reduce over the 8 chunks + add projection bias.
// ----------------------------------------------------------------------------
__global__ void fold_reduce(const float* __restrict__ bq, const float* __restrict__ bk,
                            const float* __restrict__ bv)
{
    int t = blockIdx.x * blockDim.x + threadIdx.x;
    if (t >= 3 * 13 * 512) return;
    int mat = t / (13 * 512);
    int r   = (t / 512) % 13;
    int e   = t & 511;
    if (mat == 0 && r >= 6 && r < 12) { g_A[0][r][e] = 0.f; return; }
    float s = 0.f;
#pragma unroll
    for (int c = 0; c < 8; c++) s += g_part[mat][c][r][e];
    if (r == 12) s += (mat == 0 ? bq[e] : (mat == 1 ? bk[e] : bv[e]));
    g_A[mat][r][e] = s;
}

// ----------------------------------------------------------------------------
// Precompute 2: tiny per-head matrices (log2e*SCALE prefolded; P packed).
// grid = 5, block = 256  (1254 work items)
// ----------------------------------------------------------------------------
__global__ void precompute_small(const float* __restrict__ Wp, const float* __restrict__ bp)
{
    int idx = blockIdx.x * 256 + threadIdx.x;
    const float KS = LOG2E * SCALE_EMB;
    if (idx < 576) {                                   // M[h][k][c]
        int h = idx / 72, r = idx % 72, k = r / 12, c = r % 12;
        float s = 0.f;
#pragma unroll 4
        for (int d = 0; d < 64; d++) s += g_A[0][k][h * 64 + d] * g_A[1][c][h * 64 + d];
        g_params.M[h][k][c] = KS * s;
    } else if (idx < 672) {                            // v[h][c]
        int t = idx - 576, h = t / 12, c = t % 12;
        float s = 0.f;
#pragma unroll 4
        for (int d = 0; d < 64; d++) s += g_A[0][12][h * 64 + d] * g_A[1][c][h * 64 + d];
        g_params.v[h][c] = KS * s;
    } else if (idx < 1248) {                           // Pp[h][o][c] (both branches)
        int t = idx - 672, h = t / 72, q = t % 72, o = q / 12, c = q % 12;
        float s0 = 0.f, s1 = 0.f;
#pragma unroll 4
        for (int d = 0; d < 64; d++) {
            float av = g_A[2][c][h * 64 + d];
            s0 += Wp[o * 1024 +       h * 64 + d] * av;
            s1 += Wp[o * 1024 + 512 + h * 64 + d] * av;
        }
        g_params.Pp[h][o][c] = pack2(s0, s1);
    } else if (idx < 1254) {                           // C[o]
        int o = idx - 1248;
        float s = bp[o];
#pragma unroll 4
        for (int e = 0; e < 512; e++)
            s += (Wp[o * 1024 + e] + Wp[o * 1024 + 512 + e]) * g_A[2][12][e];
        g_params.C[o] = s;
    }
}

// ----------------------------------------------------------------------------
// Main fused kernel: one CTA per 16x16 tile (512 CTAs), one thread per query s.
// 4 passes x 2 heads; each head's two branches share the f32x2 lanes.
// ----------------------------------------------------------------------------
__global__ __launch_bounds__(256, 1)
void cross_attn_main(const float* __restrict__ img1, const float* __restrict__ img2,
                     float* __restrict__ out)
{
    __shared__ __align__(16) u64 sFd[256][12];   // fcat dup-lane: (f_c, f_c), 96B rows
    __shared__ Params sp;

    int b  = blockIdx.x;
    int bi = b >> 6, th = (b >> 3) & 7, tw = b & 7;
    int s  = threadIdx.x;
    int y  = s >> 4, x = s & 15;
    int base = bi * 6 * 16384 + (th * 16 + y) * 128 + (tw * 16 + x);

    float f1r[6], f2r[6];
#pragma unroll
    for (int c = 0; c < 6; c++) {
        f1r[c] = img1[base + c * 16384];
        f2r[c] = img2[base + c * 16384];
    }
#pragma unroll
    for (int c = 0; c < 6; c++) {
        sFd[s][c]     = pack2(f1r[c], f1r[c]);
        sFd[s][6 + c] = pack2(f2r[c], f2r[c]);
    }
    {
        float* dst = (float*)&sp;
        const float* src = (const float*)&g_params;
        for (int i = s; i < (int)(sizeof(Params) / 4); i += 256) dst[i] = src[i];
    }
    __syncthreads();

    u64 outacc[6];
#pragma unroll
    for (int o = 0; o < 6; o++) outacc[o] = 0ull;

    for (int hp = 0; hp < 4; hp++) {
        int h0 = 2 * hp, h1 = h0 + 1;

        // g[c] = (branch1, branch2) logit vectors (v + f @ M), prescaled.
        u64 g0[12], g1[12];
#pragma unroll
        for (int c = 0; c < 12; c++) {
            float a1 = sp.v[h0][c], a2 = a1;
            float b1 = sp.v[h1][c], b2 = b1;
#pragma unroll
            for (int k = 0; k < 6; k++) {
                float m0 = sp.M[h0][k][c], m1 = sp.M[h1][k][c];
                a1 += f1r[k] * m0; a2 += f2r[k] * m0;
                b1 += f1r[k] * m1; b2 += f2r[k] * m1;
            }
            g0[c] = pack2(a1, a2);
            g1[c] = pack2(b1, b2);
        }

        u64 G0[12], G1[12];
#pragma unroll
        for (int c = 0; c < 12; c++) { G0[c] = 0ull; G1[c] = 0ull; }
        u64 l0 = 0ull, l1 = 0ull;   // (0.0f, 0.0f)

        // Logits are O(0.1) by construction (weights 0.02, folded twice):
        // exp without max-subtraction is exact softmax.
#pragma unroll 2
        for (int j = 0; j < 256; j++) {
            const ulonglong2* rp = (const ulonglong2*)(&sFd[j][0]);
            ulonglong2 q0 = rp[0], q1 = rp[1], q2 = rp[2];
            ulonglong2 q3 = rp[3], q4 = rp[4], q5 = rp[5];
            u64 fd0 = q0.x, fd1 = q0.y, fd2  = q1.x, fd3  = q1.y;
            u64 fd4 = q2.x, fd5 = q2.y, fd6  = q3.x, fd7  = q3.y;
            u64 fd8 = q4.x, fd9 = q4.y, fd10 = q5.x, fd11 = q5.y;

            u64 a0 = mul2(g0[0], fd0);
            u64 a1 = mul2(g1[0], fd0);
            a0 = fma2(g0[1],  fd1,  a0);  a1 = fma2(g1[1],  fd1,  a1);
            a0 = fma2(g0[2],  fd2,  a0);  a1 = fma2(g1[2],  fd2,  a1);
            a0 = fma2(g0[3],  fd3,  a0);  a1 = fma2(g1[3],  fd3,  a1);
            a0 = fma2(g0[4],  fd4,  a0);  a1 = fma2(g1[4],  fd4,  a1);
            a0 = fma2(g0[5],  fd5,  a0);  a1 = fma2(g1[5],  fd5,  a1);
            a0 = fma2(g0[6],  fd6,  a0);  a1 = fma2(g1[6],  fd6,  a1);
            a0 = fma2(g0[7],  fd7,  a0);  a1 = fma2(g1[7],  fd7,  a1);
            a0 = fma2(g0[8],  fd8,  a0);  a1 = fma2(g1[8],  fd8,  a1);
            a0 = fma2(g0[9],  fd9,  a0);  a1 = fma2(g1[9],  fd9,  a1);
            a0 = fma2(g0[10], fd10, a0);  a1 = fma2(g1[10], fd10, a1);
            a0 = fma2(g0[11], fd11, a0);  a1 = fma2(g1[11], fd11, a1);

            float e00, e01, e10, e11;
            unpack2(a0, e00, e01);
            unpack2(a1, e10, e11);
            u64 pp0 = pack2(ex2f(e00), ex2f(e01));
            u64 pp1 = pack2(ex2f(e10), ex2f(e11));
            l0 = add2(l0, pp0);
            l1 = add2(l1, pp1);

            G0[0]  = fma2(pp0, fd0,  G0[0]);   G1[0]  = fma2(pp1, fd0,  G1[0]);
            G0[1]  = fma2(pp0, fd1,  G0[1]);   G1[1]  = fma2(pp1, fd1,  G1[1]);
            G0[2]  = fma2(pp0, fd2,  G0[2]);   G1[2]  = fma2(pp1, fd2,  G1[2]);
            G0[3]  = fma2(pp0, fd3,  G0[3]);   G1[3]  = fma2(pp1, fd3,  G1[3]);
            G0[4]  = fma2(pp0, fd4,  G0[4]);   G1[4]  = fma2(pp1, fd4,  G1[4]);
            G0[5]  = fma2(pp0, fd5,  G0[5]);   G1[5]  = fma2(pp1, fd5,  G1[5]);
            G0[6]  = fma2(pp0, fd6,  G0[6]);   G1[6]  = fma2(pp1, fd6,  G1[6]);
            G0[7]  = fma2(pp0, fd7,  G0[7]);   G1[7]  = fma2(pp1, fd7,  G1[7]);
            G0[8]  = fma2(pp0, fd8,  G0[8]);   G1[8]  = fma2(pp1, fd8,  G1[8]);
            G0[9]  = fma2(pp0, fd9,  G0[9]);   G1[9]  = fma2(pp1, fd9,  G1[9]);
            G0[10] = fma2(pp0, fd10, G0[10]);  G1[10] = fma2(pp1, fd10, G1[10]);
            G0[11] = fma2(pp0, fd11, G0[11]);  G1[11] = fma2(pp1, fd11, G1[11]);
        }

        float la, lb;
        unpack2(l0, la, lb);
        u64 inv0 = pack2(rcpf(la), rcpf(lb));
        unpack2(l1, la, lb);
        u64 inv1 = pack2(rcpf(la), rcpf(lb));
#pragma unroll
        for (int c = 0; c < 12; c++) {
            G0[c] = mul2(G0[c], inv0);
            G1[c] = mul2(G1[c], inv1);
        }
#pragma unroll
        for (int o = 0; o < 6; o++) {
            u64 acc = outacc[o];
#pragma unroll
            for (int c = 0; c < 12; c++) acc = fma2(G0[c], sp.Pp[h0][o][c], acc);
#pragma unroll
            for (int c = 0; c < 12; c++) acc = fma2(G1[c], sp.Pp[h1][o][c], acc);
            outacc[o] = acc;
        }
    }

#pragma unroll
    for (int o = 0; o < 6; o++) {
        float lo, hi;
        unpack2(outacc[o], lo, hi);
        out[base + o * 16384] = sp.C[o] + lo + hi;
    }
}

// ----------------------------------------------------------------------------
extern "C" void kernel_launch(void* const* d_in, const int* in_sizes, int n_in,
                              void* d_out, int out_size)
{
    const float* img1   = (const float*)d_in[0];
    const float* img2   = (const float*)d_in[1];
    const float* W_emb  = (const float*)d_in[2];
    const float* b_emb  = (const float*)d_in[3];
    const float* W_emb2 = (const float*)d_in[4];
    const float* b_emb2 = (const float*)d_in[5];
    const float* Wq     = (const float*)d_in[6];
    const float* bq     = (const float*)d_in[7];
    const float* Wk     = (const float*)d_in[8];
    const float* bk     = (const float*)d_in[9];
    const float* Wv     = (const float*)d_in[10];
    const float* bv     = (const float*)d_in[11];
    const float* Wp     = (const float*)d_in[12];
    const float* bp     = (const float*)d_in[13];
    float* out = (float*)d_out;

    fold_partial<<<24, 512>>>(W_emb, b_emb, W_emb2, b_emb2, Wq, Wk, Wv);
    fold_reduce<<<78, 256>>>(bq, bk, bv);
    precompute_small<<<5, 256>>>(Wp, bp);
    cross_attn_main<<<512, 256>>>(img1, img2, out);
}